// round 15
// baseline (speedup 1.0000x reference)
#include <cuda_runtime.h>
#include <cuda_fp16.h>
#include <cstdint>

// ---------------------------------------------------------------------------
// BasicConvolutionBlock: sparse conv (gather-GEMM, K=27, Cin=Cout=64) + BN + ReLU
// fp16 mma.sync m16n8k16 (f32 acc) with PER-K ROW COMPACTION: only mask=1 rows
// (≈52%) enter the MMA; results scatter-add into a persistent smem f32
// accumulator via the compaction list. ~0.56x the mma instructions of dense.
//   d_in[0] feats [N,64] f32      d_in[1] W [27,64,64] f32
//   d_in[2] gamma [64]            d_in[3] beta [64]
//   d_in[4] nbr_idx [27,N] i32    d_in[5] mask [27,N] i32
// out: [N,64] f32
// ---------------------------------------------------------------------------

#define CIN   64
#define COUT  64
#define MAXK  27
#define M_TILE 128
#define CTA   256
#define BN_EPS 1e-5f

// smem layout (bytes)
#define ACC_OFF 0u           // f32 Acc[128][66] = 33792 (66 pad: bank spread + f2 align)
#define A_OFF0  33792u       // fp16 A tiles, 16384 each (128 rows x 128B)
#define A_OFF1  50176u
#define B_OFF0  66560u       // fp16 B tiles, 8192 each
#define B_OFF1  74752u
#define CL_OFF  82944u       // u16 cl[2][128]  (slot -> local row)
#define CLN_OFF 83456u       // i32 cln[2][128] (slot -> nbr index)
#define WT_OFF  84480u       // u32 wt[2][4]    (per-warp valid counts)
#define SMEM_BYTES 84608u

__device__ float  g_stats[128];                  // [0:64) sum, [64:128) sumsq
__device__ __half g_wt[MAXK * CIN * COUT];       // fp16 W, transposed [k][cout][cin]

// ---------------- helpers ---------------------------------------------------
__device__ __forceinline__ uint32_t smem_u32(const void* p) {
    uint32_t a;
    asm("{ .reg .u64 t; cvta.to.shared.u64 t, %1; cvt.u32.u64 %0, t; }"
        : "=r"(a) : "l"(p));
    return a;
}

__device__ __forceinline__ void cpa16(uint32_t dst, const void* src) {
    asm volatile("cp.async.cg.shared.global [%0], [%1], 16;"
                 :: "r"(dst), "l"(src) : "memory");
}
#define CP_COMMIT() asm volatile("cp.async.commit_group;" ::: "memory")
#define CP_WAIT0()  asm volatile("cp.async.wait_group 0;" ::: "memory")
#define CP_WAIT1()  asm volatile("cp.async.wait_group 1;" ::: "memory")

__device__ __forceinline__ uint32_t f2h2(float lo, float hi) {
    __half2 h = __floats2half2_rn(lo, hi);
    return *reinterpret_cast<uint32_t*>(&h);
}

// ---------------------------------------------------------------------------
// prep_w: blocks 0..kk-1 transpose+convert W via smem; block kk zeroes stats.
__global__ void prep_w_kernel(const float* __restrict__ w, int kk) {
    __shared__ float t[64][65];
    int k = blockIdx.x;
    if (k >= kk) {
        if (threadIdx.x < 128) g_stats[threadIdx.x] = 0.0f;
        return;
    }
    const float* ws = w + (size_t)k * CIN * COUT;
    __half* wd = g_wt + (size_t)k * CIN * COUT;
#pragma unroll
    for (int i = 0; i < 16; ++i) {
        int idx = threadIdx.x + i * 256;
        t[idx >> 6][idx & 63] = ws[idx];
    }
    __syncthreads();
#pragma unroll
    for (int i = 0; i < 16; ++i) {
        int idx = threadIdx.x + i * 256;
        int co = idx >> 6, ci = idx & 63;
        wd[idx] = __float2half_rn(t[ci][co]);
    }
}

// ---------------------------------------------------------------------------
__global__ void __launch_bounds__(CTA, 2)
conv_kernel(const float* __restrict__ feats,
            const int* __restrict__ nbr,
            const int* __restrict__ mask,
            float*     __restrict__ out,
            int n, int kk) {
    extern __shared__ char smem[];
    const uint32_t sb = smem_u32(smem);
    float* Acc = (float*)smem;
    unsigned short* cl = (unsigned short*)(smem + CL_OFF);
    int* cln = (int*)(smem + CLN_OFF);
    unsigned* wt = (unsigned*)(smem + WT_OFF);

    const int tid = threadIdx.x;
    const int warp = tid >> 5, lane = tid & 31;
    const int lr = lane >> 2, le = lane & 3;
    const int cb = blockIdx.x * M_TILE;
    const int slot = tid >> 1, hh = tid & 1;
    const uint32_t a_off[2] = {A_OFF0, A_OFF1};
    const uint32_t b_off[2] = {B_OFF0, B_OFF1};
    const unsigned lml = (1u << lane) - 1u;

    // zero Acc
    for (int i = tid; i < 128 * 66; i += CTA) Acc[i] = 0.f;

    // prefetch (mask,nbr) @ k=0 for this thread's row
    int pv1 = 0, pn1 = 0;
    if (tid < 128) {
        int g = cb + tid;
        if (g < n) { pv1 = mask[g]; pn1 = nbr[g]; }
    }
    // ballot for k=0
    int predp = 0, lpp = 0;
    if (tid < 128) {
        predp = (pv1 != 0);
        unsigned bal = __ballot_sync(0xffffffffu, predp);
        lpp = __popc(bal & lml);
        if (lane == 0) wt[warp] = __popc(bal);
    }
    __syncthreads();
    // write list(0); stage B(0)
    if (tid < 128 && predp) {
        int woff = 0;
        for (int w2 = 0; w2 < warp; ++w2) woff += wt[w2];
        int pos = woff + lpp;
        cl[pos] = (unsigned short)tid;
        cln[pos] = pn1;
    }
    if (tid >= 128) {
        const char* wsrc = (const char*)g_wt;
        int t2 = tid - 128;
#pragma unroll
        for (int i = 0; i < 4; ++i) {
            int g = t2 + i * 128, co = g >> 3, q = g & 7;
            cpa16(sb + B_OFF0 + (uint32_t)(co * 128 + ((q ^ (co & 7)) << 4)),
                  wsrc + g * 16);
        }
    }
    CP_COMMIT();
    if (kk > 1 && tid < 128) {           // prefetch @ k=1
        int g = cb + tid; pv1 = 0; pn1 = 0;
        if (g < n) { int o = n + g; pv1 = mask[o]; pn1 = nbr[o]; }
    }
    __syncthreads();                     // list(0) visible
    // gather A(0): LDG f32 -> cvt -> STS (2 threads per slot)
    {
        int v0 = wt[0] + wt[1] + wt[2] + wt[3];
        float4 fr4[8];
        bool ga = (slot < v0);
        if (ga) {
            const float4* src = (const float4*)feats + (size_t)cln[slot] * 16 + hh * 8;
#pragma unroll
            for (int j = 0; j < 8; ++j) fr4[j] = src[j];
        }
        CP_WAIT0();                      // B(0) arrived
        if (ga) {
#pragma unroll
            for (int j = 0; j < 4; ++j) {
                uint4 u;
                u.x = f2h2(fr4[2 * j].x, fr4[2 * j].y);
                u.y = f2h2(fr4[2 * j].z, fr4[2 * j].w);
                u.z = f2h2(fr4[2 * j + 1].x, fr4[2 * j + 1].y);
                u.w = f2h2(fr4[2 * j + 1].z, fr4[2 * j + 1].w);
                *(uint4*)(smem + A_OFF0 + slot * 128 +
                          ((((hh << 2) + j) ^ (slot & 7)) << 4)) = u;
            }
        }
    }
    __syncthreads();                     // A(0), B(0) ready

    for (int k = 0; k < kk; ++k) {
        const int nxt = k + 1;
        const int buf = k & 1, nbuf = nxt & 1;

        // (1) ballot list(k+1)
        int pred = 0, lp = 0;
        if (nxt < kk && tid < 128) {
            pred = (pv1 != 0);
            unsigned bal = __ballot_sync(0xffffffffu, pred);
            lp = __popc(bal & lml);
            if (lane == 0) wt[nbuf * 4 + warp] = __popc(bal);
        }
        __syncthreads();                 // (2) wt(k+1) visible; Acc RMW(k-1) done

        // (3) write list(k+1); stage B(k+1)
        if (nxt < kk) {
            if (tid < 128 && pred) {
                int woff = 0;
                for (int w2 = 0; w2 < warp; ++w2) woff += wt[nbuf * 4 + w2];
                int pos = woff + lp;
                cl[nbuf * 128 + pos] = (unsigned short)tid;
                cln[nbuf * 128 + pos] = pn1;
            }
            if (tid >= 128) {
                const char* wsrc = (const char*)(g_wt + (size_t)nxt * CIN * COUT);
                int t2 = tid - 128;
#pragma unroll
                for (int i = 0; i < 4; ++i) {
                    int g = t2 + i * 128, co = g >> 3, q = g & 7;
                    cpa16(sb + b_off[nbuf] + (uint32_t)(co * 128 + ((q ^ (co & 7)) << 4)),
                          wsrc + g * 16);
                }
            }
        }
        CP_COMMIT();
        if (nxt + 1 < kk && tid < 128) { // prefetch @ k+2
            int g = cb + tid; pv1 = 0; pn1 = 0;
            if (g < n) { int o = (nxt + 1) * n + g; pv1 = mask[o]; pn1 = nbr[o]; }
        }
        CP_WAIT1();                      // B(k) arrived (B(k+1) may fly)
        __syncthreads();                 // (4) A(k),B(k),list(k+1) visible

        const int v0 = wt[buf * 4 + 0] + wt[buf * 4 + 1] +
                       wt[buf * 4 + 2] + wt[buf * 4 + 3];

        // (4.5) issue LDG for A(k+1)
        float4 fr4[8];
        bool ga = false;
        if (nxt < kk) {
            int v1 = wt[nbuf * 4 + 0] + wt[nbuf * 4 + 1] +
                     wt[nbuf * 4 + 2] + wt[nbuf * 4 + 3];
            ga = (slot < v1);
            if (ga) {
                const float4* src = (const float4*)feats +
                                    (size_t)cln[nbuf * 128 + slot] * 16 + hh * 8;
#pragma unroll
                for (int j = 0; j < 8; ++j) fr4[j] = src[j];
            }
        }

        // (5) compute k on compacted rows
        const int sc = (v0 + 15) >> 4;
        float fr[8][4];
        if (warp < sc) {
#pragma unroll
            for (int nt = 0; nt < 8; ++nt) {
                fr[nt][0] = 0.f; fr[nt][1] = 0.f; fr[nt][2] = 0.f; fr[nt][3] = 0.f;
            }
            const char* Ap = smem + a_off[buf];
            const char* Bp = smem + b_off[buf];
            const int rbase = (warp << 4) + lr;
#pragma unroll
            for (int ks = 0; ks < 4; ++ks) {
                const uint32_t g0 = (uint32_t)((2 * ks) ^ lr) << 4;
                const uint32_t g1 = (uint32_t)((2 * ks + 1) ^ lr) << 4;
                const uint32_t ao = (uint32_t)(rbase << 7) + (uint32_t)(le << 2);
                uint32_t a0 = *(const uint32_t*)(Ap + ao + g0);
                uint32_t a1 = *(const uint32_t*)(Ap + ao + g0 + 1024);
                uint32_t a2 = *(const uint32_t*)(Ap + ao + g1);
                uint32_t a3 = *(const uint32_t*)(Ap + ao + g1 + 1024);
#pragma unroll
                for (int nt = 0; nt < 8; ++nt) {
                    const uint32_t bo = (uint32_t)((nt * 8 + lr) << 7) + (uint32_t)(le << 2);
                    uint32_t b0 = *(const uint32_t*)(Bp + bo + g0);
                    uint32_t b1 = *(const uint32_t*)(Bp + bo + g1);
                    asm volatile(
                        "mma.sync.aligned.m16n8k16.row.col.f32.f16.f16.f32 "
                        "{%0,%1,%2,%3}, {%4,%5,%6,%7}, {%8,%9}, {%0,%1,%2,%3};"
                        : "+f"(fr[nt][0]), "+f"(fr[nt][1]),
                          "+f"(fr[nt][2]), "+f"(fr[nt][3])
                        : "r"(a0), "r"(a1), "r"(a2), "r"(a3), "r"(b0), "r"(b1));
                }
            }
        }

        // (6a) cvt + STS A(k+1)
        if (ga) {
            const uint32_t ab = a_off[nbuf];
#pragma unroll
            for (int j = 0; j < 4; ++j) {
                uint4 u;
                u.x = f2h2(fr4[2 * j].x, fr4[2 * j].y);
                u.y = f2h2(fr4[2 * j].z, fr4[2 * j].w);
                u.z = f2h2(fr4[2 * j + 1].x, fr4[2 * j + 1].y);
                u.w = f2h2(fr4[2 * j + 1].z, fr4[2 * j + 1].w);
                *(uint4*)(smem + ab + slot * 128 +
                          ((((hh << 2) + j) ^ (slot & 7)) << 4)) = u;
            }
        }

        // (6b) scatter-add into Acc via list(k)
        if (warp < sc) {
            int p0 = (warp << 4) + lr, p1 = p0 + 8;
            int row0 = (p0 < v0) ? (int)cl[buf * 128 + p0] : -1;
            int row1 = (p1 < v0) ? (int)cl[buf * 128 + p1] : -1;
#pragma unroll
            for (int nt = 0; nt < 8; ++nt) {
                int c = nt * 8 + (le << 1);
                if (row0 >= 0) {
                    float2* p = (float2*)(Acc + row0 * 66 + c);
                    float2 t = *p; t.x += fr[nt][0]; t.y += fr[nt][1]; *p = t;
                }
                if (row1 >= 0) {
                    float2* p = (float2*)(Acc + row1 * 66 + c);
                    float2 t = *p; t.x += fr[nt][2]; t.y += fr[nt][3]; *p = t;
                }
            }
        }
    }
    __syncthreads();

    // ---- BN stats from Acc (untouched rows are exact zeros) ----
    {
        int c = tid & 63, rb = tid >> 6;
        float s = 0.f, q = 0.f;
        for (int r = rb * 32; r < rb * 32 + 32; ++r) {
            float x = Acc[r * 66 + c];
            s += x; q += x * x;
        }
        atomicAdd(&g_stats[c], s);
        atomicAdd(&g_stats[64 + c], q);
    }

    // ---- write conv output ----
#pragma unroll
    for (int it = 0; it < 16; ++it) {
        int idx = tid + it * CTA;               // 0..4095 float2s
        int r = idx >> 5, c2 = idx & 31;
        int g = cb + r;
        if (g < n) {
            float2 v = *(const float2*)(Acc + r * 66 + c2 * 2);
            *(float2*)(out + (size_t)g * COUT + c2 * 2) = v;
        }
    }
}

// ---------------------------------------------------------------------------
__global__ void bn_relu_kernel(float* __restrict__ out,
                               const float* __restrict__ gamma,
                               const float* __restrict__ beta,
                               int n) {
    __shared__ float sc[COUT], bi[COUT];
    const int tid = threadIdx.x;
    if (tid < COUT) {
        float inv_n = 1.0f / (float)n;
        float mean = g_stats[tid] * inv_n;
        float var = fmaxf(g_stats[64 + tid] * inv_n - mean * mean, 0.0f);
        float inv = rsqrtf(var + BN_EPS);
        float scl = gamma[tid] * inv;
        sc[tid] = scl;
        bi[tid] = beta[tid] - mean * scl;
    }
    __syncthreads();

    const int total = n * (COUT / 4);
    float4* o4 = (float4*)out;
    for (int i = blockIdx.x * blockDim.x + tid; i < total;
         i += gridDim.x * blockDim.x) {
        float4 v = o4[i];
        int c = (i & 15) << 2;
        v.x = fmaxf(fmaf(v.x, sc[c],     bi[c]),     0.f);
        v.y = fmaxf(fmaf(v.y, sc[c + 1], bi[c + 1]), 0.f);
        v.z = fmaxf(fmaf(v.z, sc[c + 2], bi[c + 2]), 0.f);
        v.w = fmaxf(fmaf(v.w, sc[c + 3], bi[c + 3]), 0.f);
        o4[i] = v;
    }
}

// ---------------------------------------------------------------------------
extern "C" void kernel_launch(void* const* d_in, const int* in_sizes, int n_in,
                              void* d_out, int out_size) {
    const float* feats = (const float*)d_in[0];
    const float* Wg    = (const float*)d_in[1];
    const float* gamma = (const float*)d_in[2];
    const float* beta  = (const float*)d_in[3];
    const int*   nbr   = (const int*)d_in[4];
    const int*   mask  = (const int*)d_in[5];
    float* out = (float*)d_out;

    const int n  = in_sizes[0] / CIN;              // 200000
    const int kk = in_sizes[1] / (CIN * COUT);     // 27

    cudaFuncSetAttribute(conv_kernel,
                         cudaFuncAttributeMaxDynamicSharedMemorySize,
                         SMEM_BYTES);

    prep_w_kernel<<<kk + 1, 256>>>(Wg, kk);        // block kk zeroes g_stats

    const int grid = (n + M_TILE - 1) / M_TILE;    // 1563
    conv_kernel<<<grid, CTA, SMEM_BYTES>>>(feats, nbr, mask, out, n, kk);

    int bn_grid = (n * (COUT / 4) + 255) / 256;
    if (bn_grid > 1184) bn_grid = 1184;
    bn_relu_kernel<<<bn_grid, 256>>>(out, gamma, beta, n);
}